// round 1
// baseline (speedup 1.0000x reference)
#include <cuda_runtime.h>

// SigLipLoss: loss = (1/N) * sum_{i,j} softplus( s_ij )
//   s_ij = LOGIT_SCALE * dot(img_i, txt_j) + LOGIT_BIAS   for i != j
//   s_ii = -(LOGIT_SCALE * dot(img_i, txt_i) + LOGIT_BIAS)
// N = 8192, D = 768, fp32.

#define NN 8192
#define DD 768
#define GRID_DIM 64           // 8192 / 128
#define NUM_BLOCKS (GRID_DIM * GRID_DIM)

__constant__ float c_scale = 2.302585092994046f;
__constant__ float c_bias  = -10.0f;

// Fixed-slot partials: fully deterministic reduction, no device alloc.
__device__ float g_partials[NUM_BLOCKS];

__global__ __launch_bounds__(256, 2)
void siglip_main_kernel(const float* __restrict__ A,   // image_features [N, D]
                        const float* __restrict__ B)   // text_features  [N, D]
{
    __shared__ float As[16][128];   // [k][m]
    __shared__ float Bs[16][128];   // [k][n]
    __shared__ float red[256];

    const int tid = threadIdx.x;
    const int tx  = tid & 15;       // n-group 0..15
    const int ty  = tid >> 4;       // m-group 0..15

    const int rowBase = blockIdx.y * 128;   // image rows
    const int colBase = blockIdx.x * 128;   // text rows

    // Global-load mapping: each thread loads 2 float4 per tile per matrix.
    const int lrow = tid >> 2;      // 0..63
    const int lc4  = tid & 3;       // 0..3  (16 floats per row = 4 float4)

    const float* Aptr = A + (size_t)(rowBase + lrow) * DD + lc4 * 4;
    const float* Bptr = B + (size_t)(colBase + lrow) * DD + lc4 * 4;

    float acc[8][8];
#pragma unroll
    for (int i = 0; i < 8; ++i)
#pragma unroll
        for (int j = 0; j < 8; ++j) acc[i][j] = 0.0f;

    // Prefetch chunk 0 into registers.
    float4 pa0 = *(const float4*)(Aptr);
    float4 pa1 = *(const float4*)(Aptr + (size_t)64 * DD);
    float4 pb0 = *(const float4*)(Bptr);
    float4 pb1 = *(const float4*)(Bptr + (size_t)64 * DD);

    for (int k0 = 0; k0 < DD; k0 += 16) {
        __syncthreads();   // previous compute done before overwriting smem

        // Store prefetched chunk, transposed to [k][m]/[k][n].
        const int kb = lc4 * 4;
        As[kb + 0][lrow] = pa0.x;  As[kb + 1][lrow] = pa0.y;
        As[kb + 2][lrow] = pa0.z;  As[kb + 3][lrow] = pa0.w;
        As[kb + 0][lrow + 64] = pa1.x;  As[kb + 1][lrow + 64] = pa1.y;
        As[kb + 2][lrow + 64] = pa1.z;  As[kb + 3][lrow + 64] = pa1.w;
        Bs[kb + 0][lrow] = pb0.x;  Bs[kb + 1][lrow] = pb0.y;
        Bs[kb + 2][lrow] = pb0.z;  Bs[kb + 3][lrow] = pb0.w;
        Bs[kb + 0][lrow + 64] = pb1.x;  Bs[kb + 1][lrow + 64] = pb1.y;
        Bs[kb + 2][lrow + 64] = pb1.z;  Bs[kb + 3][lrow + 64] = pb1.w;

        __syncthreads();

        // Prefetch next chunk (hidden under the FFMA block below).
        if (k0 + 16 < DD) {
            pa0 = *(const float4*)(Aptr + k0 + 16);
            pa1 = *(const float4*)(Aptr + (size_t)64 * DD + k0 + 16);
            pb0 = *(const float4*)(Bptr + k0 + 16);
            pb1 = *(const float4*)(Bptr + (size_t)64 * DD + k0 + 16);
        }

#pragma unroll
        for (int kk = 0; kk < 16; ++kk) {
            float4 a0 = *(const float4*)&As[kk][ty * 8];
            float4 a1 = *(const float4*)&As[kk][ty * 8 + 4];
            float4 b0 = *(const float4*)&Bs[kk][tx * 8];
            float4 b1 = *(const float4*)&Bs[kk][tx * 8 + 4];
            float a[8] = {a0.x, a0.y, a0.z, a0.w, a1.x, a1.y, a1.z, a1.w};
            float b[8] = {b0.x, b0.y, b0.z, b0.w, b1.x, b1.y, b1.z, b1.w};
#pragma unroll
            for (int i = 0; i < 8; ++i)
#pragma unroll
                for (int j = 0; j < 8; ++j)
                    acc[i][j] = fmaf(a[i], b[j], acc[i][j]);
        }
    }

    // Epilogue: logits -> softplus terms -> per-thread sum.
    float lsum = 0.0f;
#pragma unroll
    for (int i = 0; i < 8; ++i) {
        const int row = rowBase + ty * 8 + i;
#pragma unroll
        for (int j = 0; j < 8; ++j) {
            const int col = colBase + tx * 8 + j;
            float z = fmaf(acc[i][j], c_scale, c_bias);
            if (row == col) z = -z;     // diagonal: label = +1
            // stable softplus(z) = max(z,0) + log(1 + exp(-|z|))
            lsum += fmaxf(z, 0.0f) + __logf(1.0f + __expf(-fabsf(z)));
        }
    }

    // Deterministic block reduction.
    red[tid] = lsum;
    __syncthreads();
#pragma unroll
    for (int off = 128; off >= 32; off >>= 1) {
        if (tid < off) red[tid] += red[tid + off];
        __syncthreads();
    }
    if (tid < 32) {
        float v = red[tid];
#pragma unroll
        for (int off = 16; off > 0; off >>= 1)
            v += __shfl_down_sync(0xFFFFFFFFu, v, off);
        if (tid == 0)
            g_partials[blockIdx.y * GRID_DIM + blockIdx.x] = v;
    }
}

__global__ void siglip_finalize_kernel(float* __restrict__ out)
{
    __shared__ double sd[256];
    const int t = threadIdx.x;
    double s = 0.0;
    for (int i = t; i < NUM_BLOCKS; i += 256)
        s += (double)g_partials[i];
    sd[t] = s;
    __syncthreads();
#pragma unroll
    for (int off = 128; off > 0; off >>= 1) {
        if (t < off) sd[t] += sd[t + off];
        __syncthreads();
    }
    if (t == 0)
        out[0] = (float)(sd[0] / (double)NN);
}

extern "C" void kernel_launch(void* const* d_in, const int* in_sizes, int n_in,
                              void* d_out, int out_size)
{
    const float* image = (const float*)d_in[0];
    const float* text  = (const float*)d_in[1];
    float* out = (float*)d_out;

    dim3 grid(GRID_DIM, GRID_DIM);
    siglip_main_kernel<<<grid, 256>>>(image, text);
    siglip_finalize_kernel<<<1, 256>>>(out);
}

// round 3
// speedup vs baseline: 6.4214x; 6.4214x over previous
#include <cuda_runtime.h>
#include <cuda_bf16.h>
#include <cstdint>

// SigLipLoss: loss = (1/N) * sum_ij softplus(s_ij),
//   s_ij = SCALE*dot(img_i,txt_j)+BIAS, sign-flipped on diagonal.
// Round 2: bf16 mma.sync (m16n8k16) GEMM, cp.async 3-stage pipeline.
// NOTE: harness PTX target is sm_103 (no 'a') -> tcgen05 unavailable.

#define NN 8192
#define DD 768
#define BM 128
#define BN 128
#define BK 32
#define STAGES 3
#define NITER (DD / BK)              // 24
#define GRIDX (NN / BN)              // 64
#define GRIDY (NN / BM)              // 64
#define NUM_BLOCKS (GRIDX * GRIDY)   // 4096

#define ROWB 80                      // smem row pitch bytes (32 bf16 + 8 pad)
#define ATILE_B (BM * ROWB)          // 10240
#define STAGE_B (2 * ATILE_B)        // 20480
#define SMEM_TOTAL (STAGES * STAGE_B + 128)

__device__ __align__(16) __nv_bfloat16 g_Abf[NN * DD];
__device__ __align__(16) __nv_bfloat16 g_Bbf[NN * DD];
__device__ float g_partials[NUM_BLOCKS];

__device__ __forceinline__ uint32_t smem_u32(const void* p) {
    uint32_t r;
    asm("{ .reg .u64 t; cvta.to.shared.u64 t, %1; cvt.u32.u64 %0, t; }"
        : "=r"(r) : "l"(p));
    return r;
}
__device__ __forceinline__ void cpa16(uint32_t dst, const void* src) {
    asm volatile("cp.async.cg.shared.global [%0], [%1], 16;"
                 :: "r"(dst), "l"(__cvta_generic_to_global(src)) : "memory");
}
__device__ __forceinline__ void ldm_x4(uint32_t* r, uint32_t addr) {
    asm volatile("ldmatrix.sync.aligned.m8n8.x4.shared.b16 {%0,%1,%2,%3}, [%4];"
                 : "=r"(r[0]), "=r"(r[1]), "=r"(r[2]), "=r"(r[3]) : "r"(addr));
}
__device__ __forceinline__ void mma16816(float* c, const uint32_t* a,
                                         const uint32_t* b) {
    asm volatile(
        "mma.sync.aligned.m16n8k16.row.col.f32.bf16.bf16.f32 "
        "{%0,%1,%2,%3}, {%4,%5,%6,%7}, {%8,%9}, {%0,%1,%2,%3};"
        : "+f"(c[0]), "+f"(c[1]), "+f"(c[2]), "+f"(c[3])
        : "r"(a[0]), "r"(a[1]), "r"(a[2]), "r"(a[3]), "r"(b[0]), "r"(b[1]));
}

__global__ void convert_kernel(const float* __restrict__ A,
                               const float* __restrict__ B) {
    const int total4 = NN * DD / 4;
    const int stride = gridDim.x * blockDim.x;
    __nv_bfloat162* pa = (__nv_bfloat162*)g_Abf;
    __nv_bfloat162* pb = (__nv_bfloat162*)g_Bbf;
    for (int i = blockIdx.x * blockDim.x + threadIdx.x; i < total4; i += stride) {
        float4 a = ((const float4*)A)[i];
        float4 b = ((const float4*)B)[i];
        pa[2 * i + 0] = __floats2bfloat162_rn(a.x, a.y);
        pa[2 * i + 1] = __floats2bfloat162_rn(a.z, a.w);
        pb[2 * i + 0] = __floats2bfloat162_rn(b.x, b.y);
        pb[2 * i + 1] = __floats2bfloat162_rn(b.z, b.w);
    }
}

__global__ __launch_bounds__(256, 2) void siglip_mma_kernel() {
    extern __shared__ char smem_raw[];
    const uint32_t sbase = smem_u32(smem_raw);

    const int tid  = threadIdx.x;
    const int wid  = tid >> 5;
    const int lane = tid & 31;
    const int warp_m = wid & 3;          // 4 m-groups of 32 rows
    const int warp_n = wid >> 2;         // 2 n-groups of 64 cols
    const int rowBase = blockIdx.y * BM;
    const int colBase = blockIdx.x * BN;

    // ---- global->smem fill mapping (2 chunks of 16B per matrix per thread) ----
    const int r0 = tid >> 2;             // 0..63
    const int c16 = tid & 3;             // 16B column (BK=32 bf16 = 64B = 4 chunks)
    const __nv_bfloat16* aS0 = g_Abf + (size_t)(rowBase + r0) * DD + c16 * 8;
    const __nv_bfloat16* aS1 = g_Abf + (size_t)(rowBase + r0 + 64) * DD + c16 * 8;
    const __nv_bfloat16* bS0 = g_Bbf + (size_t)(colBase + r0) * DD + c16 * 8;
    const __nv_bfloat16* bS1 = g_Bbf + (size_t)(colBase + r0 + 64) * DD + c16 * 8;
    const uint32_t dA0 = r0 * ROWB + c16 * 16;
    const uint32_t dA1 = (r0 + 64) * ROWB + c16 * 16;

    // ---- ldmatrix per-lane offsets ----
    // A (x4): lanes 0-7 m0-7/k0 | 8-15 m8-15/k0 | 16-23 m0-7/k8 | 24-31 m8-15/k8
    const uint32_t aOff = (warp_m * 32 + (lane & 7) + ((lane >> 3) & 1) * 8) * ROWB
                        + (lane >> 4) * 16;
    // B (x4): lanes 0-7 n0-7/k0 | 8-15 n0-7/k8 | 16-23 n8-15/k0 | 24-31 n8-15/k8
    const uint32_t bOff = (warp_n * 64 + (lane & 7) + ((lane >> 4) & 1) * 8) * ROWB
                        + ((lane >> 3) & 1) * 16;

    float acc[2][8][4];
#pragma unroll
    for (int mt = 0; mt < 2; ++mt)
#pragma unroll
        for (int nt = 0; nt < 8; ++nt)
#pragma unroll
            for (int v = 0; v < 4; ++v) acc[mt][nt][v] = 0.0f;

    // ---- prologue: fill stages 0,1 ----
#pragma unroll
    for (int s = 0; s < STAGES - 1; ++s) {
        const uint32_t base = sbase + s * STAGE_B;
        const int ke = s * BK;
        cpa16(base + dA0, aS0 + ke);
        cpa16(base + dA1, aS1 + ke);
        cpa16(base + ATILE_B + dA0, bS0 + ke);
        cpa16(base + ATILE_B + dA1, bS1 + ke);
        asm volatile("cp.async.commit_group;" ::: "memory");
    }

#pragma unroll 1
    for (int it = 0; it < NITER; ++it) {
        if (it < NITER - 1) asm volatile("cp.async.wait_group 1;" ::: "memory");
        else                asm volatile("cp.async.wait_group 0;" ::: "memory");
        __syncthreads();

        // fill stage it+2 (buffer freed by compute of iter it-1)
        if (it + STAGES - 1 < NITER) {
            const uint32_t base = sbase + ((it + 2) % STAGES) * STAGE_B;
            const int ke = (it + 2) * BK;
            cpa16(base + dA0, aS0 + ke);
            cpa16(base + dA1, aS1 + ke);
            cpa16(base + ATILE_B + dA0, bS0 + ke);
            cpa16(base + ATILE_B + dA1, bS1 + ke);
            asm volatile("cp.async.commit_group;" ::: "memory");
        }

        const uint32_t sA = sbase + (it % STAGES) * STAGE_B;
        const uint32_t sB = sA + ATILE_B;
#pragma unroll
        for (int kk = 0; kk < 2; ++kk) {
            uint32_t a[2][4], b[4][4];
#pragma unroll
            for (int mt = 0; mt < 2; ++mt)
                ldm_x4(a[mt], sA + aOff + mt * (16 * ROWB) + kk * 32);
#pragma unroll
            for (int np = 0; np < 4; ++np)
                ldm_x4(b[np], sB + bOff + np * (16 * ROWB) + kk * 32);
#pragma unroll
            for (int mt = 0; mt < 2; ++mt)
#pragma unroll
                for (int nt = 0; nt < 8; ++nt)
                    mma16816(acc[mt][nt], a[mt], &b[nt >> 1][(nt & 1) * 2]);
        }
    }

    // ---- epilogue: softplus + deterministic reduction ----
    const float SCALE = 2.302585092994046f, BIAS = -10.0f;
    float lsum = 0.0f;
#pragma unroll
    for (int mt = 0; mt < 2; ++mt) {
        const int row0 = rowBase + warp_m * 32 + mt * 16 + (lane >> 2);
#pragma unroll
        for (int nt = 0; nt < 8; ++nt) {
            const int col0 = colBase + warp_n * 64 + nt * 8 + (lane & 3) * 2;
#pragma unroll
            for (int v = 0; v < 4; ++v) {
                const int row = row0 + (v >> 1) * 8;
                const int col = col0 + (v & 1);
                float z = fmaf(acc[mt][nt][v], SCALE, BIAS);
                if (row == col) z = -z;
                lsum += fmaxf(z, 0.0f) + __logf(1.0f + __expf(-fabsf(z)));
            }
        }
    }

#pragma unroll
    for (int off = 16; off > 0; off >>= 1)
        lsum += __shfl_down_sync(0xFFFFFFFFu, lsum, off);
    float* red = (float*)(smem_raw + STAGES * STAGE_B);
    __syncthreads();                 // tiles no longer needed; reuse region safely
    if (lane == 0) red[wid] = lsum;
    __syncthreads();
    if (tid == 0) {
        float t = 0.0f;
#pragma unroll
        for (int i = 0; i < 8; ++i) t += red[i];
        g_partials[blockIdx.y * GRIDX + blockIdx.x] = t;
    }
}

__global__ void siglip_finalize_kernel(float* __restrict__ out) {
    __shared__ double sd[256];
    const int t = threadIdx.x;
    double s = 0.0;
    for (int i = t; i < NUM_BLOCKS; i += 256)
        s += (double)g_partials[i];
    sd[t] = s;
    __syncthreads();
#pragma unroll
    for (int off = 128; off > 0; off >>= 1) {
        if (t < off) sd[t] += sd[t + off];
        __syncthreads();
    }
    if (t == 0) out[0] = (float)(sd[0] / (double)NN);
}

extern "C" void kernel_launch(void* const* d_in, const int* in_sizes, int n_in,
                              void* d_out, int out_size) {
    cudaFuncSetAttribute(siglip_mma_kernel,
                         cudaFuncAttributeMaxDynamicSharedMemorySize, SMEM_TOTAL);
    convert_kernel<<<2048, 256>>>((const float*)d_in[0], (const float*)d_in[1]);
    dim3 grid(GRIDX, GRIDY);
    siglip_mma_kernel<<<grid, 256, SMEM_TOTAL>>>();
    siglip_finalize_kernel<<<1, 256>>>((float*)d_out);
}

// round 4
// speedup vs baseline: 6.6544x; 1.0363x over previous
#include <cuda_runtime.h>
#include <cuda_bf16.h>
#include <cstdint>

// SigLipLoss: loss = (1/N) * sum_ij softplus(s_ij), sign-flip on diagonal.
// Round 3: persistent CTAs (grid=148), 256x128 tiles, bf16 mma.sync,
// continuous 4-stage cp.async pipeline across tiles, XOR-swizzled smem.

#define NN 8192
#define DD 768
#define BM 256
#define BN 128
#define BK 32
#define NTILES (NN / BM * NN / BN)    // 32*64 = 2048
#define KITERS (DD / BK)              // 24
#define NCTA 148
#define ROWBYTES (DD * 2)             // 1536

#define A_B   (BM * 64)               // 16384 bytes per stage for A
#define STAGE_B ((BM + BN) * 64)      // 24576
#define STAGES 4
#define SMEM_TOTAL (STAGES * STAGE_B + 256)

__device__ __align__(16) __nv_bfloat16 g_Abf[NN * DD];
__device__ __align__(16) __nv_bfloat16 g_Bbf[NN * DD];
__device__ float g_partials[NTILES];

__device__ __forceinline__ uint32_t smem_u32(const void* p) {
    uint32_t r;
    asm("{ .reg .u64 t; cvta.to.shared.u64 t, %1; cvt.u32.u64 %0, t; }"
        : "=r"(r) : "l"(p));
    return r;
}
__device__ __forceinline__ void cpa16(uint32_t dst, const void* src) {
    asm volatile("cp.async.cg.shared.global [%0], [%1], 16;"
                 :: "r"(dst), "l"(__cvta_generic_to_global(src)) : "memory");
}
__device__ __forceinline__ void ldm_x4(uint32_t* r, uint32_t addr) {
    asm volatile("ldmatrix.sync.aligned.m8n8.x4.shared.b16 {%0,%1,%2,%3}, [%4];"
                 : "=r"(r[0]), "=r"(r[1]), "=r"(r[2]), "=r"(r[3]) : "r"(addr));
}
__device__ __forceinline__ void mma16816(float* c, const uint32_t* a,
                                         const uint32_t* b) {
    asm volatile(
        "mma.sync.aligned.m16n8k16.row.col.f32.bf16.bf16.f32 "
        "{%0,%1,%2,%3}, {%4,%5,%6,%7}, {%8,%9}, {%0,%1,%2,%3};"
        : "+f"(c[0]), "+f"(c[1]), "+f"(c[2]), "+f"(c[3])
        : "r"(a[0]), "r"(a[1]), "r"(a[2]), "r"(a[3]), "r"(b[0]), "r"(b[1]));
}

__global__ void convert_kernel(const float* __restrict__ A,
                               const float* __restrict__ B) {
    const int total4 = NN * DD / 4;
    const int stride = gridDim.x * blockDim.x;
    __nv_bfloat162* pa = (__nv_bfloat162*)g_Abf;
    __nv_bfloat162* pb = (__nv_bfloat162*)g_Bbf;
    for (int i = blockIdx.x * blockDim.x + threadIdx.x; i < total4; i += stride) {
        float4 a = ((const float4*)A)[i];
        float4 b = ((const float4*)B)[i];
        pa[2 * i + 0] = __floats2bfloat162_rn(a.x, a.y);
        pa[2 * i + 1] = __floats2bfloat162_rn(a.z, a.w);
        pb[2 * i + 0] = __floats2bfloat162_rn(b.x, b.y);
        pb[2 * i + 1] = __floats2bfloat162_rn(b.z, b.w);
    }
}

__global__ __launch_bounds__(512, 1) void siglip_mma_kernel() {
    extern __shared__ char smem_raw[];
    uint32_t sbase = smem_u32(smem_raw);
    sbase = (sbase + 127u) & ~127u;

    const int tid  = threadIdx.x;
    const int wid  = tid >> 5;
    const int lane = tid & 31;
    const int warp_m = wid & 7;          // 8 m-groups of 32 rows
    const int warp_n = wid >> 3;         // 2 n-groups of 64 cols
    const int cta = blockIdx.x;

    const int ntiles = (NTILES - cta + NCTA - 1) / NCTA;
    const int C = ntiles * KITERS;       // total k-chunks this CTA consumes

    // ---- producer mapping: 3x 16B chunks per thread per k-chunk ----
    const int r0 = tid >> 2;             // 0..127
    const int c4 = tid & 3;              // 16B chunk within 64B row
    const uint32_t swz = (uint32_t)((c4 ^ ((r0 >> 1) & 3)) * 16);
    const uint32_t dstA0 = r0 * 64 + swz;
    const uint32_t dstA1 = dstA0 + 128 * 64;
    const uint32_t dstB0 = A_B + r0 * 64 + swz;
    const uint32_t cB16 = c4 * 16;

    int pKB = 0, pG = cta, ps = 0;
    const char* bA0 = (const char*)g_Abf
        + ((size_t)(pG >> 6) * BM + r0) * ROWBYTES + cB16;
    const char* bA1 = bA0 + (size_t)128 * ROWBYTES;
    const char* bB0 = (const char*)g_Bbf
        + ((size_t)(pG & 63) * BN + r0) * ROWBYTES + cB16;

#define ISSUE() do {                                                     \
        const uint32_t stb = sbase + (uint32_t)ps * STAGE_B;             \
        cpa16(stb + dstA0, bA0 + pKB);                                   \
        cpa16(stb + dstA1, bA1 + pKB);                                   \
        cpa16(stb + dstB0, bB0 + pKB);                                   \
        asm volatile("cp.async.commit_group;" ::: "memory");             \
        ps = (ps + 1) & 3;                                               \
        pKB += 64;                                                       \
        if (pKB == DD * 2) {                                             \
            pKB = 0; pG += NCTA;                                         \
            if (pG < NTILES) {                                           \
                bA0 = (const char*)g_Abf                                 \
                    + ((size_t)(pG >> 6) * BM + r0) * ROWBYTES + cB16;   \
                bA1 = bA0 + (size_t)128 * ROWBYTES;                      \
                bB0 = (const char*)g_Bbf                                 \
                    + ((size_t)(pG & 63) * BN + r0) * ROWBYTES + cB16;   \
            }                                                            \
        }                                                                \
    } while (0)

    // ---- ldmatrix per-lane addresses ----
    const int rowA = warp_m * 32 + (lane & 15);
    const uint32_t xa = (uint32_t)(((lane & 15) >> 1) & 3);
    const uint32_t ca = (uint32_t)(lane >> 4);
    const uint32_t aBase = rowA * 64;
    const uint32_t swzA0 = ((0 + ca) ^ xa) * 16;   // kk=0
    const uint32_t swzA1 = ((2 + ca) ^ xa) * 16;   // kk=1

    const int rowB = warp_n * 64 + (lane & 7) + ((lane >> 4) & 1) * 8;
    const uint32_t xb = (uint32_t)((rowB >> 1) & 3);
    const uint32_t cb = (uint32_t)((lane >> 3) & 1);
    const uint32_t bBase = A_B + rowB * 64;
    const uint32_t swzB0 = ((0 + cb) ^ xb) * 16;
    const uint32_t swzB1 = ((2 + cb) ^ xb) * 16;

    float* red = (float*)(smem_raw + STAGES * STAGE_B + 128);

    int issued = 0;
#pragma unroll
    for (int i = 0; i < 3; ++i) { ISSUE(); ++issued; }

    int ch = 0;
    int g = cta;
#pragma unroll 1
    for (int t = 0; t < ntiles; ++t, g += NCTA) {
        float acc[2][8][4];
#pragma unroll
        for (int mt = 0; mt < 2; ++mt)
#pragma unroll
            for (int nt = 0; nt < 8; ++nt)
#pragma unroll
                for (int v = 0; v < 4; ++v) acc[mt][nt][v] = 0.0f;

#pragma unroll 1
        for (int it = 0; it < KITERS; ++it, ++ch) {
            if (ch + 3 <= C) asm volatile("cp.async.wait_group 2;" ::: "memory");
            else             asm volatile("cp.async.wait_group 0;" ::: "memory");
            __syncthreads();
            if (issued < C) { ISSUE(); ++issued; }

            const uint32_t sS = sbase + (uint32_t)(ch & 3) * STAGE_B;
            uint32_t a[2][4], b[4][4];
#pragma unroll
            for (int kk = 0; kk < 2; ++kk) {
                const uint32_t sa = kk ? swzA1 : swzA0;
                const uint32_t sb = kk ? swzB1 : swzB0;
#pragma unroll
                for (int mt = 0; mt < 2; ++mt)
                    ldm_x4(a[mt], sS + aBase + mt * 1024 + sa);
#pragma unroll
                for (int np = 0; np < 4; ++np)
                    ldm_x4(b[np], sS + bBase + np * 1024 + sb);
#pragma unroll
                for (int mt = 0; mt < 2; ++mt)
#pragma unroll
                    for (int nt = 0; nt < 8; ++nt)
                        mma16816(acc[mt][nt], a[mt], &b[nt >> 1][(nt & 1) * 2]);
            }
        }

        // ---- tile epilogue: softplus + deterministic reduction ----
        const float SCALE = 2.302585092994046f, BIAS = -10.0f;
        const int rowBase = (g >> 6) * BM;
        const int colBase = (g & 63) * BN;
        float lsum = 0.0f;
#pragma unroll
        for (int mt = 0; mt < 2; ++mt) {
            const int row0 = rowBase + warp_m * 32 + mt * 16 + (lane >> 2);
#pragma unroll
            for (int nt = 0; nt < 8; ++nt) {
                const int col0 = colBase + warp_n * 64 + nt * 8 + (lane & 3) * 2;
#pragma unroll
                for (int v = 0; v < 4; ++v) {
                    const int row = row0 + (v >> 1) * 8;
                    const int col = col0 + (v & 1);
                    float z = fmaf(acc[mt][nt][v], SCALE, BIAS);
                    if (row == col) z = -z;
                    lsum += fmaxf(z, 0.0f) + __logf(1.0f + __expf(-fabsf(z)));
                }
            }
        }
#pragma unroll
        for (int off = 16; off > 0; off >>= 1)
            lsum += __shfl_down_sync(0xFFFFFFFFu, lsum, off);
        if (lane == 0) red[wid] = lsum;
        __syncthreads();
        if (tid == 0) {
            float s = 0.0f;
#pragma unroll
            for (int i = 0; i < 16; ++i) s += red[i];
            g_partials[g] = s;
        }
        __syncthreads();
    }
#undef ISSUE
}

__global__ void siglip_finalize_kernel(float* __restrict__ out) {
    __shared__ double sd[256];
    const int t = threadIdx.x;
    double s = 0.0;
    for (int i = t; i < NTILES; i += 256)
        s += (double)g_partials[i];
    sd[t] = s;
    __syncthreads();
#pragma unroll
    for (int off = 128; off > 0; off >>= 1) {
        if (t < off) sd[t] += sd[t + off];
        __syncthreads();
    }
    if (t == 0) out[0] = (float)(sd[0] / (double)NN);
}

extern "C" void kernel_launch(void* const* d_in, const int* in_sizes, int n_in,
                              void* d_out, int out_size) {
    cudaFuncSetAttribute(siglip_mma_kernel,
                         cudaFuncAttributeMaxDynamicSharedMemorySize, SMEM_TOTAL);
    convert_kernel<<<2048, 256>>>((const float*)d_in[0], (const float*)d_in[1]);
    siglip_mma_kernel<<<NCTA, 512, SMEM_TOTAL>>>();
    siglip_finalize_kernel<<<1, 256>>>((float*)d_out);
}